// round 10
// baseline (speedup 1.0000x reference)
#include <cuda_runtime.h>
#include <cuda_bf16.h>

// NBVLoss: weighted BCE full reduction, single fused kernel.
//   loss = 1.6 * sum_{t==1} bce + 0.4 * sum_{t==0} bce
//   bce  = -(t*max(log p, -100) + (1-t)*max(log(1-p), -100))
//
// t is exactly 0/1 -> one log per element, in the lg2 domain:
//   contrib = -(w*ln2) * max(lg2(x), -100/ln2),
//   (x, w) = t ? (p, 1.6) : (1-p, 0.4)
//
// R10 change (single variable vs R9): block-CONTIGUOUS chunking instead of
// grid-stride. Each block walks one contiguous region of each array
// (4 KB per warp-iteration), concentrating per-SM traffic for DRAM
// row-buffer / L2-sector locality. Everything else frozen at the R7/R9
// validated optimum (82.4 us, 6.43 TB/s, chip streaming ceiling).
//
// Frozen evidence (R1-R9):
//  - __launch_bounds__(256, 8): 32 regs -> 8 CTAs/SM -> grid 1184 = ONE
//    wave on 148 SMs (R2: straggler wave costs +16 us).
//  - No manual unroll (beat MLP_p1=4/8 in R5/R6). One log (R4, -2 us).
//  - Fused deterministic last-block finalize (counter self-resets).

constexpr int BLOCKS  = 1184;   // 148 SMs * 8 CTAs
constexpr int THREADS = 256;

__device__ __forceinline__ float bce_w(float p, float t) {
    constexpr float W1   = 1.6f * 0.69314718055994530942f;    // 1.6*ln2
    constexpr float W0   = 0.4f * 0.69314718055994530942f;    // 0.4*ln2
    constexpr float CLMP = -100.0f / 0.69314718055994530942f; // -100/ln2
    bool one = (t != 0.0f);
    float x = one ? p  : (1.0f - p);
    float w = one ? W1 : W0;
    float l2 = fmaxf(__log2f(x), CLMP);   // __log2f(0) = -inf -> clamped
    return -w * l2;
}

__device__ double g_partial[BLOCKS];
__device__ unsigned int g_arrive_count;   // zero-init; reset by last block

__global__ void __launch_bounds__(THREADS, 8)
bce_fused_kernel(const float4* __restrict__ pred,
                 const float4* __restrict__ targ,
                 int n4, int n_tail_base, int n_total,
                 float* __restrict__ out)
{
    float local = 0.0f;

    // Block-contiguous chunk: block b owns float4 range [b*chunk, (b+1)*chunk).
    const int chunk = (n4 + BLOCKS - 1) / BLOCKS;
    const int start = blockIdx.x * chunk;
    const int end   = min(start + chunk, n4);

    for (int idx = start + threadIdx.x; idx < end; idx += THREADS) {
        float4 pv = __ldcs(&pred[idx]);   // streaming: read-once data
        float4 tv = __ldcs(&targ[idx]);
        local += bce_w(pv.x, tv.x);
        local += bce_w(pv.y, tv.y);
        local += bce_w(pv.z, tv.z);
        local += bce_w(pv.w, tv.w);
    }

    // Scalar tail (n not divisible by 4) — one thread, deterministic.
    if (blockIdx.x == 0 && threadIdx.x == 0) {
        const float* ps = (const float*)pred;
        const float* ts = (const float*)targ;
        for (int i = n_tail_base; i < n_total; i++)
            local += bce_w(ps[i], ts[i]);
    }

    // Warp reduce (float), then cross-warp in double (fixed order per block).
    #pragma unroll
    for (int off = 16; off > 0; off >>= 1)
        local += __shfl_down_sync(0xFFFFFFFFu, local, off);

    __shared__ double s_warp[THREADS / 32];
    __shared__ bool s_is_last;
    int wid = threadIdx.x >> 5;
    int lid = threadIdx.x & 31;
    if (lid == 0) s_warp[wid] = (double)local;
    __syncthreads();

    if (threadIdx.x == 0) {
        double acc = 0.0;
        #pragma unroll
        for (int w = 0; w < THREADS / 32; w++) acc += s_warp[w];
        g_partial[blockIdx.x] = acc;
        // Make the partial globally visible before signaling arrival.
        __threadfence();
        unsigned int prev = atomicAdd(&g_arrive_count, 1u);
        s_is_last = (prev == (unsigned int)(BLOCKS - 1));
    }
    __syncthreads();

    if (s_is_last) {
        // Last block reduces all partials in a FIXED order -> deterministic.
        __shared__ double s_fin[THREADS];
        double v = 0.0;
        for (int i = threadIdx.x; i < BLOCKS; i += THREADS)
            v += g_partial[i];
        s_fin[threadIdx.x] = v;
        __syncthreads();
        #pragma unroll
        for (int off = THREADS / 2; off > 0; off >>= 1) {
            if (threadIdx.x < off) s_fin[threadIdx.x] += s_fin[threadIdx.x + off];
            __syncthreads();
        }
        if (threadIdx.x == 0) {
            out[0] = (float)s_fin[0];
            g_arrive_count = 0;   // reset for next graph replay
        }
    }
}

extern "C" void kernel_launch(void* const* d_in, const int* in_sizes, int n_in,
                              void* d_out, int out_size)
{
    const float4* pred = (const float4*)d_in[0];
    const float4* targ = (const float4*)d_in[1];
    float* out = (float*)d_out;

    int n  = in_sizes[0];        // 16384*4096 = 67108864
    int n4 = n >> 2;
    int tail_base = n4 << 2;

    bce_fused_kernel<<<BLOCKS, THREADS>>>(pred, targ, n4, tail_base, n, out);
}

// round 11
// speedup vs baseline: 1.0750x; 1.0750x over previous
#include <cuda_runtime.h>
#include <cuda_bf16.h>

// NBVLoss: weighted BCE full reduction, single fused kernel. FINAL (R9 config,
// reverted after R10's locality experiment regressed).
//   loss = 1.6 * sum_{t==1} bce + 0.4 * sum_{t==0} bce
//   bce  = -(t*max(log p, -100) + (1-t)*max(log(1-p), -100))
//
// t is exactly 0/1 -> one log per element, computed in the lg2 domain:
//   contrib = -(w*ln2) * max(lg2(x), -100/ln2),
//   (x, w) = t ? (p, 1.6) : (1-p, 0.4)
//
// Full evidence trail (R1-R10):
//  - Pure HBM-streaming: 536.9 MB read / 4 B written. Best achieved
//    6.43 TB/s = measured LTS path ceiling -> ~82.4 us IS the roofline.
//  - GRID-STRIDE beats block-contiguous chunks (R10: 88.6 us, DRAM 76%):
//    interleaved addresses spread evenly over the L2 slice hash.
//  - __launch_bounds__(256, 8): 32 regs -> 8 CTAs/SM -> grid 1184 = ONE
//    wave on 148 SMs (R2: a 7-CTA straggler wave costs +16 us).
//  - No manual unroll: compiler schedule beat MLP_p1=4/8 (R5/R6).
//  - One log not two (R4: issue 50%->27%, -2 us); lg2 domain folds the
//    ln2 FMUL into compile-time weights (R9: fma 11%->9%).
//  - Fused last-block finalize: removes second launch; deterministic
//    (fixed-order reduction; arrival counter self-resets for graph replay).

constexpr int BLOCKS  = 1184;   // 148 SMs * 8 CTAs
constexpr int THREADS = 256;

// ln2 and the clamp mapped into the lg2 domain.
__device__ __forceinline__ float lg2_clamped_neg(float x, bool one) {
    constexpr float W1   = 1.6f * 0.69314718055994530942f;   // 1.6*ln2
    constexpr float W0   = 0.4f * 0.69314718055994530942f;   // 0.4*ln2
    constexpr float CLMP = -100.0f / 0.69314718055994530942f; // -100/ln2
    float w  = one ? W1 : W0;
    float l2 = fmaxf(__log2f(x), CLMP);   // __log2f(0) = -inf -> clamped
    return -w * l2;
}

__device__ __forceinline__ float bce_w(float p, float t) {
    bool one = (t != 0.0f);
    float x = one ? p : (1.0f - p);
    return lg2_clamped_neg(x, one);
}

__device__ double g_partial[BLOCKS];
__device__ unsigned int g_arrive_count;   // zero-init; reset by last block

__global__ void __launch_bounds__(THREADS, 8)
bce_fused_kernel(const float4* __restrict__ pred,
                 const float4* __restrict__ targ,
                 int n4, int n_tail_base, int n_total,
                 float* __restrict__ out)
{
    float local = 0.0f;

    int idx = blockIdx.x * THREADS + threadIdx.x;
    const int stride = BLOCKS * THREADS;
    for (; idx < n4; idx += stride) {
        float4 pv = __ldcs(&pred[idx]);   // streaming: read-once data
        float4 tv = __ldcs(&targ[idx]);
        local += bce_w(pv.x, tv.x);
        local += bce_w(pv.y, tv.y);
        local += bce_w(pv.z, tv.z);
        local += bce_w(pv.w, tv.w);
    }

    // Scalar tail (n not divisible by 4) — one thread, deterministic.
    if (blockIdx.x == 0 && threadIdx.x == 0) {
        const float* ps = (const float*)pred;
        const float* ts = (const float*)targ;
        for (int i = n_tail_base; i < n_total; i++)
            local += bce_w(ps[i], ts[i]);
    }

    // Warp reduce (float), then cross-warp in double (fixed order per block).
    #pragma unroll
    for (int off = 16; off > 0; off >>= 1)
        local += __shfl_down_sync(0xFFFFFFFFu, local, off);

    __shared__ double s_warp[THREADS / 32];
    __shared__ bool s_is_last;
    int wid = threadIdx.x >> 5;
    int lid = threadIdx.x & 31;
    if (lid == 0) s_warp[wid] = (double)local;
    __syncthreads();

    if (threadIdx.x == 0) {
        double acc = 0.0;
        #pragma unroll
        for (int w = 0; w < THREADS / 32; w++) acc += s_warp[w];
        g_partial[blockIdx.x] = acc;
        // Make the partial globally visible before signaling arrival.
        __threadfence();
        unsigned int prev = atomicAdd(&g_arrive_count, 1u);
        s_is_last = (prev == (unsigned int)(BLOCKS - 1));
    }
    __syncthreads();

    if (s_is_last) {
        // Last block reduces all partials in a FIXED order -> deterministic.
        __shared__ double s_fin[THREADS];
        double v = 0.0;
        for (int i = threadIdx.x; i < BLOCKS; i += THREADS)
            v += g_partial[i];
        s_fin[threadIdx.x] = v;
        __syncthreads();
        #pragma unroll
        for (int off = THREADS / 2; off > 0; off >>= 1) {
            if (threadIdx.x < off) s_fin[threadIdx.x] += s_fin[threadIdx.x + off];
            __syncthreads();
        }
        if (threadIdx.x == 0) {
            out[0] = (float)s_fin[0];
            g_arrive_count = 0;   // reset for next graph replay
        }
    }
}

extern "C" void kernel_launch(void* const* d_in, const int* in_sizes, int n_in,
                              void* d_out, int out_size)
{
    const float4* pred = (const float4*)d_in[0];
    const float4* targ = (const float4*)d_in[1];
    float* out = (float*)d_out;

    int n  = in_sizes[0];        // 16384*4096 = 67108864
    int n4 = n >> 2;
    int tail_base = n4 << 2;

    bce_fused_kernel<<<BLOCKS, THREADS>>>(pred, targ, n4, tail_base, n, out);
}